// round 1
// baseline (speedup 1.0000x reference)
#include <cuda_runtime.h>
#include <cstdint>

#define TOKENS 64
#define IN_F   8192
#define OUT_F  8192
#define NGROUPS (IN_F / 8)   // 1024
#define OBLK   64

// scratch: xh in [group][token][8] layout, y in [token][out] layout
__device__ float g_xh[NGROUPS * TOKENS * 8];   // 2 MB
__device__ float g_y [TOKENS * OUT_F];         // 2 MB

// 1/sqrt(8192)
#define INV_SQRT_8192 0.011048543456039806f

// ---------------------------------------------------------------------------
// Kernel A: xh = FWHT(x * SU) * (1/sqrt(IN_F) * Wscale), written transposed
// into [g][t][j] layout. One block per token.
// ---------------------------------------------------------------------------
__global__ __launch_bounds__(512) void fwht_in_kernel(
    const float* __restrict__ x,
    const float* __restrict__ SU,
    const float* __restrict__ Wscale)
{
    __shared__ float s[IN_F];           // 32 KB
    const int t = blockIdx.x;
    const float* xr = x + (size_t)t * IN_F;

    for (int i = threadIdx.x; i < IN_F; i += blockDim.x)
        s[i] = xr[i] * SU[i];
    __syncthreads();

    for (int h = 1; h < IN_F; h <<= 1) {
        for (int p = threadIdx.x; p < IN_F / 2; p += blockDim.x) {
            int i = ((p & ~(h - 1)) << 1) | (p & (h - 1));
            float u = s[i], v = s[i + h];
            s[i]     = u + v;
            s[i + h] = u - v;
        }
        __syncthreads();
    }

    const float scale = INV_SQRT_8192 * Wscale[0];
    for (int k = threadIdx.x; k < IN_F; k += blockDim.x) {
        int g = k >> 3, j = k & 7;
        g_xh[g * (TOKENS * 8) + t * 8 + j] = s[k] * scale;
    }
}

// ---------------------------------------------------------------------------
// Kernel B: y[t][o] = sum_k xh[t][k] * grid[Qidxs[o][k/8]][k%8]
// Block = 64 outputs x 64 tokens. 256 threads: tx = token (0..63),
// ty = 0..3, each thread owns 16 consecutive outputs (ty*16 .. ty*16+15).
// Codebook staged in shared as float4 pairs; Qidxs read 4 groups at a time
// (int4, broadcast across the warp); xh read as 2x float4 per group.
// ---------------------------------------------------------------------------
__global__ __launch_bounds__(256) void gemm_kernel(
    const int*   __restrict__ Qidxs,
    const float* __restrict__ grid)
{
    __shared__ float4 grid_s[512];      // 256 codes x 32 B = 8 KB
    const int tid = threadIdx.x;
    for (int i = tid; i < 512; i += 256)
        grid_s[i] = ((const float4*)grid)[i];
    __syncthreads();

    const int tx    = tid & 63;          // token
    const int ty    = tid >> 6;          // 0..3
    const int oBase = blockIdx.x * OBLK + ty * 16;

    float acc[16];
#pragma unroll
    for (int i = 0; i < 16; i++) acc[i] = 0.0f;

    for (int g0 = 0; g0 < NGROUPS; g0 += 4) {
        // xh for 4 groups, this token: 32 floats = 8 float4 loads
        float4 xv[8];
#pragma unroll
        for (int u = 0; u < 4; u++) {
            const float4* p = (const float4*)(g_xh + (size_t)(g0 + u) * (TOKENS * 8) + tx * 8);
            xv[2 * u]     = p[0];
            xv[2 * u + 1] = p[1];
        }

#pragma unroll
        for (int i = 0; i < 16; i++) {
            const int4 q = *(const int4*)(Qidxs + (size_t)(oBase + i) * NGROUPS + g0);
            float a = acc[i];
            {
                const float4 w0 = grid_s[q.x * 2], w1 = grid_s[q.x * 2 + 1];
                a = fmaf(xv[0].x, w0.x, a); a = fmaf(xv[0].y, w0.y, a);
                a = fmaf(xv[0].z, w0.z, a); a = fmaf(xv[0].w, w0.w, a);
                a = fmaf(xv[1].x, w1.x, a); a = fmaf(xv[1].y, w1.y, a);
                a = fmaf(xv[1].z, w1.z, a); a = fmaf(xv[1].w, w1.w, a);
            }
            {
                const float4 w0 = grid_s[q.y * 2], w1 = grid_s[q.y * 2 + 1];
                a = fmaf(xv[2].x, w0.x, a); a = fmaf(xv[2].y, w0.y, a);
                a = fmaf(xv[2].z, w0.z, a); a = fmaf(xv[2].w, w0.w, a);
                a = fmaf(xv[3].x, w1.x, a); a = fmaf(xv[3].y, w1.y, a);
                a = fmaf(xv[3].z, w1.z, a); a = fmaf(xv[3].w, w1.w, a);
            }
            {
                const float4 w0 = grid_s[q.z * 2], w1 = grid_s[q.z * 2 + 1];
                a = fmaf(xv[4].x, w0.x, a); a = fmaf(xv[4].y, w0.y, a);
                a = fmaf(xv[4].z, w0.z, a); a = fmaf(xv[4].w, w0.w, a);
                a = fmaf(xv[5].x, w1.x, a); a = fmaf(xv[5].y, w1.y, a);
                a = fmaf(xv[5].z, w1.z, a); a = fmaf(xv[5].w, w1.w, a);
            }
            {
                const float4 w0 = grid_s[q.w * 2], w1 = grid_s[q.w * 2 + 1];
                a = fmaf(xv[6].x, w0.x, a); a = fmaf(xv[6].y, w0.y, a);
                a = fmaf(xv[6].z, w0.z, a); a = fmaf(xv[6].w, w0.w, a);
                a = fmaf(xv[7].x, w1.x, a); a = fmaf(xv[7].y, w1.y, a);
                a = fmaf(xv[7].z, w1.z, a); a = fmaf(xv[7].w, w1.w, a);
            }
            acc[i] = a;
        }
    }

    float* yout = g_y + (size_t)tx * OUT_F + oBase;
#pragma unroll
    for (int i = 0; i < 16; i++) yout[i] = acc[i];
}

// ---------------------------------------------------------------------------
// Kernel C: out = FWHT(y) * (1/sqrt(OUT_F)) * SV + bias. One block per token.
// ---------------------------------------------------------------------------
__global__ __launch_bounds__(512) void fwht_out_kernel(
    const float* __restrict__ SV,
    const float* __restrict__ bias,
    float* __restrict__ out)
{
    __shared__ float s[OUT_F];          // 32 KB
    const int t = blockIdx.x;
    const float* yr = g_y + (size_t)t * OUT_F;

    for (int i = threadIdx.x; i < OUT_F; i += blockDim.x)
        s[i] = yr[i];
    __syncthreads();

    for (int h = 1; h < OUT_F; h <<= 1) {
        for (int p = threadIdx.x; p < OUT_F / 2; p += blockDim.x) {
            int i = ((p & ~(h - 1)) << 1) | (p & (h - 1));
            float u = s[i], v = s[i + h];
            s[i]     = u + v;
            s[i + h] = u - v;
        }
        __syncthreads();
    }

    float* orow = out + (size_t)t * OUT_F;
    for (int i = threadIdx.x; i < OUT_F; i += blockDim.x)
        orow[i] = s[i] * INV_SQRT_8192 * SV[i] + bias[i];
}

// ---------------------------------------------------------------------------
// launch
// Inputs (metadata order): x, SU, SV, grid, Wscale, bias, Qidxs
// ---------------------------------------------------------------------------
extern "C" void kernel_launch(void* const* d_in, const int* in_sizes, int n_in,
                              void* d_out, int out_size)
{
    const float* x      = (const float*)d_in[0];
    const float* SU     = (const float*)d_in[1];
    const float* SV     = (const float*)d_in[2];
    const float* grid   = (const float*)d_in[3];
    const float* Wscale = (const float*)d_in[4];
    const float* bias   = (const float*)d_in[5];
    const int*   Qidxs  = (const int*)  d_in[6];
    float*       out    = (float*)d_out;

    fwht_in_kernel<<<TOKENS, 512>>>(x, SU, Wscale);
    gemm_kernel<<<OUT_F / OBLK, 256>>>(Qidxs, grid);
    fwht_out_kernel<<<TOKENS, 512>>>(SV, bias, out);
}

// round 3
// speedup vs baseline: 6.5504x; 6.5504x over previous
#include <cuda_runtime.h>
#include <cuda_fp16.h>
#include <cstdint>

#define TOKENS 64
#define IN_F   8192
#define OUT_F  8192
#define NGROUPS (IN_F / 8)     // 1024
#define KT_TILES (IN_F / 16)   // 512 k16 tiles
#define KSPLIT 2
#define NBLK   128             // N per block (8 warps x N16)

// A fragments: [kt][mt][lane] -> uint4 (4 regs of m16k16 fp16 frag)
__device__ uint4 g_xa[KT_TILES * 4 * 32];            // 1 MB
// partial outputs per K-split: [split][token][out]
__device__ float g_part[KSPLIT * TOKENS * OUT_F];    // 4 MB

#define INV_SQRT_8192 0.011048543456039806f

// ---------------------------------------------------------------------------
// Kernel A: FWHT(x*SU)*scale -> fp16, packed directly in mma A-fragment layout.
// One block per token.
// ---------------------------------------------------------------------------
__global__ __launch_bounds__(512) void fwht_in_kernel(
    const float* __restrict__ x,
    const float* __restrict__ SU,
    const float* __restrict__ Wscale)
{
    __shared__ float s[IN_F];
    const int t = blockIdx.x;
    const float* xr = x + (size_t)t * IN_F;

    for (int i = threadIdx.x; i < IN_F; i += blockDim.x)
        s[i] = xr[i] * SU[i];
    __syncthreads();

    for (int h = 1; h < IN_F; h <<= 1) {
        for (int p = threadIdx.x; p < IN_F / 2; p += blockDim.x) {
            int i = ((p & ~(h - 1)) << 1) | (p & (h - 1));
            float u = s[i], v = s[i + h];
            s[i]     = u + v;
            s[i + h] = u - v;
        }
        __syncthreads();
    }

    const float scale = INV_SQRT_8192 * Wscale[0];
    const int mt   = t >> 4;
    const int mrow = t & 15;
    uint32_t* xa = (uint32_t*)g_xa;
    // each idx handles one even k-pair -> one half2 (one frag register slot)
    for (int idx = threadIdx.x; idx < IN_F / 2; idx += blockDim.x) {
        const int k0 = idx * 2;
        const int kt = k0 >> 4;
        const int r  = (k0 >> 3) & 1;                 // k-half within tile
        const int lane = ((mrow & 7) << 2) | ((k0 >> 1) & 3);
        const int reg  = (r << 1) | (mrow >> 3);
        __half2 h = __floats2half2_rn(s[k0] * scale, s[k0 + 1] * scale);
        xa[(((kt * 4 + mt) * 32 + lane) << 2) + reg] = *(uint32_t*)&h;
    }
}

// ---------------------------------------------------------------------------
// Kernel B: fused codebook-decode + fp16 mma.sync GEMM.
// grid = (OUT_F/NBLK, KSPLIT). block = 256 (8 warps). warp = M64 x N16.
// B fragments decoded straight into registers from the codebook in smem.
// ---------------------------------------------------------------------------
__device__ __forceinline__ void mma16816(float c[4], const uint4& a,
                                         uint32_t b0, uint32_t b1)
{
    asm volatile(
        "mma.sync.aligned.m16n8k16.row.col.f32.f16.f16.f32 "
        "{%0,%1,%2,%3},{%4,%5,%6,%7},{%8,%9},{%0,%1,%2,%3};\n"
        : "+f"(c[0]), "+f"(c[1]), "+f"(c[2]), "+f"(c[3])
        : "r"(a.x), "r"(a.y), "r"(a.z), "r"(a.w), "r"(b0), "r"(b1));
}

__global__ __launch_bounds__(256) void gemm_kernel(
    const int*   __restrict__ Qidxs,
    const float* __restrict__ grid)
{
    __shared__ uint32_t cb[256 * 4];     // codebook as half2: [code][pair]
    const int tid = threadIdx.x;
    for (int i = tid; i < 1024; i += 256) {
        int c = i >> 2, j = i & 3;
        __half2 h = __floats2half2_rn(grid[c * 8 + 2 * j], grid[c * 8 + 2 * j + 1]);
        cb[i] = *(uint32_t*)&h;
    }
    __syncthreads();

    const int lane = tid & 31;
    const int w    = tid >> 5;
    const int l4   = lane & 3;
    const int lq   = lane >> 2;
    const int oW   = blockIdx.x * NBLK + w * 16;
    const int split = blockIdx.y;

    const int ktBase = split * (KT_TILES / KSPLIT);
    const int ktEnd  = ktBase + (KT_TILES / KSPLIT);

    // per-lane Qidxs row pointers for the two n8 tiles (int2 = 2 groups)
    const int2* qp0 = (const int2*)(Qidxs + (size_t)(oW + lq) * NGROUPS);
    const int2* qp1 = (const int2*)(Qidxs + (size_t)(oW + 8 + lq) * NGROUPS);

    float acc[2][4][4];
#pragma unroll
    for (int n = 0; n < 2; n++)
#pragma unroll
        for (int m = 0; m < 4; m++)
#pragma unroll
            for (int r = 0; r < 4; r++) acc[n][m][r] = 0.0f;

    // prime the pipeline
    uint4 a_c[4];
    int2  q_c[2];
#pragma unroll
    for (int m = 0; m < 4; m++)
        a_c[m] = g_xa[(ktBase * 4 + m) * 32 + lane];
    q_c[0] = qp0[ktBase];
    q_c[1] = qp1[ktBase];

    for (int kt = ktBase; kt < ktEnd; kt++) {
        // prefetch next step
        const int ktn = (kt + 1 < ktEnd) ? kt + 1 : kt;
        uint4 a_n[4];
        int2  q_n[2];
#pragma unroll
        for (int m = 0; m < 4; m++)
            a_n[m] = g_xa[(ktn * 4 + m) * 32 + lane];
        q_n[0] = qp0[ktn];
        q_n[1] = qp1[ktn];

        // decode B fragments from codebook (registers, no STS)
        const uint32_t b00 = cb[(q_c[0].x << 2) | l4];
        const uint32_t b01 = cb[(q_c[0].y << 2) | l4];
        const uint32_t b10 = cb[(q_c[1].x << 2) | l4];
        const uint32_t b11 = cb[(q_c[1].y << 2) | l4];

#pragma unroll
        for (int m = 0; m < 4; m++) {
            mma16816(acc[0][m], a_c[m], b00, b01);
            mma16816(acc[1][m], a_c[m], b10, b11);
        }

#pragma unroll
        for (int m = 0; m < 4; m++) a_c[m] = a_n[m];
        q_c[0] = q_n[0];
        q_c[1] = q_n[1];
    }

    // store: C frag lane mapping -> t = mt*16 + lq (+8), o = oW + n*8 + 2*l4
    float* base = g_part + (size_t)split * TOKENS * OUT_F;
#pragma unroll
    for (int n = 0; n < 2; n++) {
        const int o = oW + n * 8 + 2 * l4;
#pragma unroll
        for (int m = 0; m < 4; m++) {
            const int t0 = m * 16 + lq;
            float2 v0 = make_float2(acc[n][m][0], acc[n][m][1]);
            float2 v1 = make_float2(acc[n][m][2], acc[n][m][3]);
            *(float2*)&base[(size_t)t0 * OUT_F + o]       = v0;
            *(float2*)&base[(size_t)(t0 + 8) * OUT_F + o] = v1;
        }
    }
}

// ---------------------------------------------------------------------------
// Kernel C: sum K-split partials, FWHT, * SV/sqrt + bias. One block per token.
// ---------------------------------------------------------------------------
__global__ __launch_bounds__(512) void fwht_out_kernel(
    const float* __restrict__ SV,
    const float* __restrict__ bias,
    float* __restrict__ out)
{
    __shared__ float s[OUT_F];
    const int t = blockIdx.x;
    const float* p0 = g_part + (size_t)t * OUT_F;
    const float* p1 = g_part + (size_t)(TOKENS + t) * OUT_F;

    for (int i = threadIdx.x; i < OUT_F; i += blockDim.x)
        s[i] = p0[i] + p1[i];
    __syncthreads();

    for (int h = 1; h < OUT_F; h <<= 1) {
        for (int p = threadIdx.x; p < OUT_F / 2; p += blockDim.x) {
            int i = ((p & ~(h - 1)) << 1) | (p & (h - 1));
            float u = s[i], v = s[i + h];
            s[i]     = u + v;
            s[i + h] = u - v;
        }
        __syncthreads();
    }

    float* orow = out + (size_t)t * OUT_F;
    for (int i = threadIdx.x; i < OUT_F; i += blockDim.x)
        orow[i] = s[i] * INV_SQRT_8192 * SV[i] + bias[i];
}

// ---------------------------------------------------------------------------
// Inputs (metadata order): x, SU, SV, grid, Wscale, bias, Qidxs
// ---------------------------------------------------------------------------
extern "C" void kernel_launch(void* const* d_in, const int* in_sizes, int n_in,
                              void* d_out, int out_size)
{
    const float* x      = (const float*)d_in[0];
    const float* SU     = (const float*)d_in[1];
    const float* SV     = (const float*)d_in[2];
    const float* grid   = (const float*)d_in[3];
    const float* Wscale = (const float*)d_in[4];
    const float* bias   = (const float*)d_in[5];
    const int*   Qidxs  = (const int*)  d_in[6];
    float*       out    = (float*)d_out;

    fwht_in_kernel<<<TOKENS, 512>>>(x, SU, Wscale);
    dim3 ggrid(OUT_F / NBLK, KSPLIT);
    gemm_kernel<<<ggrid, 256>>>(Qidxs, grid);
    fwht_out_kernel<<<TOKENS, 512>>>(SV, bias, out);
}

// round 4
// speedup vs baseline: 9.4325x; 1.4400x over previous
#include <cuda_runtime.h>
#include <cuda_fp16.h>
#include <cstdint>

#define TOKENS 64
#define IN_F   8192
#define OUT_F  8192
#define NGROUPS (IN_F / 8)     // 1024
#define KT_TILES (IN_F / 16)   // 512 k16 tiles
#define KSPLIT 4
#define NBLK   64              // N per block (4 warps x N16)

// A fragments: [kt][mt][lane] -> uint4 (4 regs of m16k16 fp16 frag)
__device__ uint4 g_xa[KT_TILES * 4 * 32];            // 1 MB
// partial outputs per K-split: [split][token][out]
__device__ float g_part[KSPLIT * TOKENS * OUT_F];    // 8 MB

#define INV_SQRT_8192 0.011048543456039806f

// XOR bank swizzle on low 5 bits
__device__ __forceinline__ int SW(int i) {
    return (i & ~31) | ((i ^ (i >> 5)) & 31);
}

// in-register radix-2^L FWHT over array a[N]
#define FWHT_REG(a, N)                                            \
    _Pragma("unroll")                                             \
    for (int h = 1; h < (N); h <<= 1) {                           \
        _Pragma("unroll")                                         \
        for (int i = 0; i < (N); i++) {                           \
            if (!(i & h)) {                                       \
                float u = a[i], v = a[i ^ h];                     \
                a[i] = u + v; a[i ^ h] = u - v;                   \
            }                                                     \
        }                                                         \
    }

// ---------------------------------------------------------------------------
// Kernel A: FWHT(x*SU)*scale -> fp16, packed directly in mma A-fragment layout.
// One block per token, 256 threads, 32 elems/thread, 3 register phases:
//   A: stride 256 (h=256..4096), B: stride 32 (h=32..128), C: contiguous (h=1..16)
// ---------------------------------------------------------------------------
__global__ __launch_bounds__(256) void fwht_in_kernel(
    const float* __restrict__ x,
    const float* __restrict__ SU,
    const float* __restrict__ Wscale)
{
    __shared__ float s[IN_F];                 // 32 KB
    const int t   = blockIdx.x;
    const int tid = threadIdx.x;
    const float* xr = x + (size_t)t * IN_F;

    // phase A: stride-256 radix-32
    float a[32];
#pragma unroll
    for (int j = 0; j < 32; j++) {
        const int idx = tid + 256 * j;
        a[j] = xr[idx] * SU[idx];
    }
    FWHT_REG(a, 32)
#pragma unroll
    for (int j = 0; j < 32; j++)
        s[SW(tid + 256 * j)] = a[j];
    __syncthreads();

    // phase B: stride-32 radix-8, 4 groups per thread
    const int low = tid & 31;
    const int gb  = (tid >> 5) * 4;
    float b[4][8];
#pragma unroll
    for (int gg = 0; gg < 4; gg++)
#pragma unroll
        for (int j = 0; j < 8; j++)
            b[gg][j] = s[SW((gb + gg) * 256 + j * 32 + low)];
#pragma unroll
    for (int gg = 0; gg < 4; gg++) {
        FWHT_REG(b[gg], 8)
    }
    __syncthreads();   // protect reads before overwrite
#pragma unroll
    for (int gg = 0; gg < 4; gg++)
#pragma unroll
        for (int j = 0; j < 8; j++)
            s[SW((gb + gg) * 256 + j * 32 + low)] = b[gg][j];
    __syncthreads();

    // phase C: contiguous radix-32 + epilogue pack
    float c[32];
#pragma unroll
    for (int i = 0; i < 32; i++)
        c[i] = s[SW(tid * 32 + i)];
    FWHT_REG(c, 32)

    const float scale = INV_SQRT_8192 * Wscale[0];
    const int mt   = t >> 4;
    const int mrow = t & 15;
    uint32_t* xa = (uint32_t*)g_xa;
#pragma unroll
    for (int p = 0; p < 16; p++) {
        const int k0   = tid * 32 + 2 * p;
        const int kt   = k0 >> 4;
        const int r    = (k0 >> 3) & 1;
        const int lane = ((mrow & 7) << 2) | ((k0 >> 1) & 3);
        const int reg  = (r << 1) | (mrow >> 3);
        __half2 h = __floats2half2_rn(c[2 * p] * scale, c[2 * p + 1] * scale);
        xa[(((kt * 4 + mt) * 32 + lane) << 2) + reg] = *(uint32_t*)&h;
    }
}

// ---------------------------------------------------------------------------
// Kernel B: fused codebook-decode + fp16 mma.sync GEMM.
// grid = (OUT_F/NBLK, KSPLIT). block = 128 (4 warps). warp = M64 x N16.
// Register prefetch distance 2 on both A frags and Qidxs.
// ---------------------------------------------------------------------------
__device__ __forceinline__ void mma16816(float c[4], const uint4& a,
                                         uint32_t b0, uint32_t b1)
{
    asm volatile(
        "mma.sync.aligned.m16n8k16.row.col.f32.f16.f16.f32 "
        "{%0,%1,%2,%3},{%4,%5,%6,%7},{%8,%9},{%0,%1,%2,%3};\n"
        : "+f"(c[0]), "+f"(c[1]), "+f"(c[2]), "+f"(c[3])
        : "r"(a.x), "r"(a.y), "r"(a.z), "r"(a.w), "r"(b0), "r"(b1));
}

__global__ __launch_bounds__(128) void gemm_kernel(
    const int*   __restrict__ Qidxs,
    const float* __restrict__ grid)
{
    __shared__ uint32_t cb[256 * 4];     // codebook as half2: [code][pair]
    const int tid = threadIdx.x;
    for (int i = tid; i < 1024; i += 128) {
        int c = i >> 2, j = i & 3;
        __half2 h = __floats2half2_rn(grid[c * 8 + 2 * j], grid[c * 8 + 2 * j + 1]);
        cb[i] = *(uint32_t*)&h;
    }
    __syncthreads();

    const int lane = tid & 31;
    const int w    = tid >> 5;
    const int l4   = lane & 3;
    const int lq   = lane >> 2;
    const int oW   = blockIdx.x * NBLK + w * 16;
    const int split = blockIdx.y;

    const int ktBase = split * (KT_TILES / KSPLIT);   // 128 tiles per split
    const int ktEnd  = ktBase + (KT_TILES / KSPLIT);

    const int2* qp0 = (const int2*)(Qidxs + (size_t)(oW + lq) * NGROUPS);
    const int2* qp1 = (const int2*)(Qidxs + (size_t)(oW + 8 + lq) * NGROUPS);

    float acc[2][4][4];
#pragma unroll
    for (int n = 0; n < 2; n++)
#pragma unroll
        for (int m = 0; m < 4; m++)
#pragma unroll
            for (int r = 0; r < 4; r++) acc[n][m][r] = 0.0f;

    // double-buffer, prefetch distance 2
    uint4 aB[2][4];
    int2  qB[2][2];
#pragma unroll
    for (int m = 0; m < 4; m++) {
        aB[0][m] = g_xa[((ktBase    ) * 4 + m) * 32 + lane];
        aB[1][m] = g_xa[((ktBase + 1) * 4 + m) * 32 + lane];
    }
    qB[0][0] = qp0[ktBase];     qB[0][1] = qp1[ktBase];
    qB[1][0] = qp0[ktBase + 1]; qB[1][1] = qp1[ktBase + 1];

    for (int kt = ktBase; kt < ktEnd; kt += 2) {
        // ---- sub-iter 0: consume buf0 (kt), refill with kt+2 ----
        {
            const uint32_t b00 = cb[(qB[0][0].x << 2) | l4];
            const uint32_t b01 = cb[(qB[0][0].y << 2) | l4];
            const uint32_t b10 = cb[(qB[0][1].x << 2) | l4];
            const uint32_t b11 = cb[(qB[0][1].y << 2) | l4];
#pragma unroll
            for (int m = 0; m < 4; m++) {
                mma16816(acc[0][m], aB[0][m], b00, b01);
                mma16816(acc[1][m], aB[0][m], b10, b11);
            }
            const int ktn = (kt + 2 < ktEnd) ? kt + 2 : ktEnd - 1;
#pragma unroll
            for (int m = 0; m < 4; m++)
                aB[0][m] = g_xa[(ktn * 4 + m) * 32 + lane];
            qB[0][0] = qp0[ktn];
            qB[0][1] = qp1[ktn];
        }
        // ---- sub-iter 1: consume buf1 (kt+1), refill with kt+3 ----
        {
            const uint32_t b00 = cb[(qB[1][0].x << 2) | l4];
            const uint32_t b01 = cb[(qB[1][0].y << 2) | l4];
            const uint32_t b10 = cb[(qB[1][1].x << 2) | l4];
            const uint32_t b11 = cb[(qB[1][1].y << 2) | l4];
#pragma unroll
            for (int m = 0; m < 4; m++) {
                mma16816(acc[0][m], aB[1][m], b00, b01);
                mma16816(acc[1][m], aB[1][m], b10, b11);
            }
            const int ktn = (kt + 3 < ktEnd) ? kt + 3 : ktEnd - 1;
#pragma unroll
            for (int m = 0; m < 4; m++)
                aB[1][m] = g_xa[(ktn * 4 + m) * 32 + lane];
            qB[1][0] = qp0[ktn];
            qB[1][1] = qp1[ktn];
        }
    }

    // store: C frag lane mapping -> t = mt*16 + lq (+8), o = oW + n*8 + 2*l4
    float* base = g_part + (size_t)split * TOKENS * OUT_F;
#pragma unroll
    for (int n = 0; n < 2; n++) {
        const int o = oW + n * 8 + 2 * l4;
#pragma unroll
        for (int m = 0; m < 4; m++) {
            const int t0 = m * 16 + lq;
            float2 v0 = make_float2(acc[n][m][0], acc[n][m][1]);
            float2 v1 = make_float2(acc[n][m][2], acc[n][m][3]);
            *(float2*)&base[(size_t)t0 * OUT_F + o]       = v0;
            *(float2*)&base[(size_t)(t0 + 8) * OUT_F + o] = v1;
        }
    }
}

// ---------------------------------------------------------------------------
// Kernel C: sum KSPLIT partials, FWHT (register-radix), * SV/sqrt + bias.
// One block per token, 256 threads.
// ---------------------------------------------------------------------------
__global__ __launch_bounds__(256) void fwht_out_kernel(
    const float* __restrict__ SV,
    const float* __restrict__ bias,
    float* __restrict__ out)
{
    __shared__ float s[OUT_F];
    const int t   = blockIdx.x;
    const int tid = threadIdx.x;
    const float* p0 = g_part + (size_t)(0 * TOKENS + t) * OUT_F;
    const float* p1 = g_part + (size_t)(1 * TOKENS + t) * OUT_F;
    const float* p2 = g_part + (size_t)(2 * TOKENS + t) * OUT_F;
    const float* p3 = g_part + (size_t)(3 * TOKENS + t) * OUT_F;

    // phase A: stride-256 radix-32 (input = sum of partials)
    float a[32];
#pragma unroll
    for (int j = 0; j < 32; j++) {
        const int idx = tid + 256 * j;
        a[j] = (p0[idx] + p1[idx]) + (p2[idx] + p3[idx]);
    }
    FWHT_REG(a, 32)
#pragma unroll
    for (int j = 0; j < 32; j++)
        s[SW(tid + 256 * j)] = a[j];
    __syncthreads();

    // phase B: stride-32 radix-8
    const int low = tid & 31;
    const int gb  = (tid >> 5) * 4;
    float b[4][8];
#pragma unroll
    for (int gg = 0; gg < 4; gg++)
#pragma unroll
        for (int j = 0; j < 8; j++)
            b[gg][j] = s[SW((gb + gg) * 256 + j * 32 + low)];
#pragma unroll
    for (int gg = 0; gg < 4; gg++) {
        FWHT_REG(b[gg], 8)
    }
    __syncthreads();
#pragma unroll
    for (int gg = 0; gg < 4; gg++)
#pragma unroll
        for (int j = 0; j < 8; j++)
            s[SW((gb + gg) * 256 + j * 32 + low)] = b[gg][j];
    __syncthreads();

    // phase C: contiguous radix-32 + epilogue
    float c[32];
#pragma unroll
    for (int i = 0; i < 32; i++)
        c[i] = s[SW(tid * 32 + i)];
    FWHT_REG(c, 32)

    float* orow = out + (size_t)t * OUT_F;
#pragma unroll
    for (int i = 0; i < 32; i++) {
        const int idx = tid * 32 + i;
        orow[idx] = c[i] * INV_SQRT_8192 * SV[idx] + bias[idx];
    }
}

// ---------------------------------------------------------------------------
// Inputs (metadata order): x, SU, SV, grid, Wscale, bias, Qidxs
// ---------------------------------------------------------------------------
extern "C" void kernel_launch(void* const* d_in, const int* in_sizes, int n_in,
                              void* d_out, int out_size)
{
    const float* x      = (const float*)d_in[0];
    const float* SU     = (const float*)d_in[1];
    const float* SV     = (const float*)d_in[2];
    const float* grid   = (const float*)d_in[3];
    const float* Wscale = (const float*)d_in[4];
    const float* bias   = (const float*)d_in[5];
    const int*   Qidxs  = (const int*)  d_in[6];
    float*       out    = (float*)d_out;

    fwht_in_kernel<<<TOKENS, 256>>>(x, SU, Wscale);
    dim3 ggrid(OUT_F / NBLK, KSPLIT);
    gemm_kernel<<<ggrid, 128>>>(Qidxs, grid);
    fwht_out_kernel<<<TOKENS, 256>>>(SV, bias, out);
}